// round 4
// baseline (speedup 1.0000x reference)
#include <cuda_runtime.h>

// 2-layer LSTM (H=30, IN=1) + linear head, B=512, T=2048.
// Block = TWO batch elements, 128 threads = 4 warps. Warp w owns gate TYPE w
// (0=i,1=f,2=g,3=o), lane u owns unit u. Weight rows are register-resident
// (f32x2 packed) and SHARED between the two batch elements -> two independent
// dependency chains per warp, one barrier per step for two elements.
//
// Software pipeline across layers (validated R2): iteration t computes
// L1 gates for step t and L2 gates for step t-1 (both need only h1[t-1],
// h2[t-2]) -> ONE __syncthreads per iteration. Gate buffers double-buffered.
// State updates computed redundantly per warp (warp-private h copies).
// FC head: warp 0 reduces elem A, warp 1 reduces elem B.

#define Hs 30
#define Ts 2048
#define Bs 512

typedef unsigned long long ull;

__device__ __forceinline__ ull pk(float lo, float hi) {
    ull r; asm("mov.b64 %0, {%1, %2};" : "=l"(r) : "f"(lo), "f"(hi)); return r;
}
__device__ __forceinline__ void fma2(ull& d, ull a, ull b) {
    asm("fma.rn.f32x2 %0, %1, %2, %3;" : "=l"(d) : "l"(a), "l"(b), "l"(d));
}
__device__ __forceinline__ ull add2(ull a, ull b) {
    ull r; asm("add.rn.f32x2 %0, %1, %2;" : "=l"(r) : "l"(a), "l"(b)); return r;
}
__device__ __forceinline__ float hadd(ull a) {
    float lo, hi; asm("mov.b64 {%0, %1}, %2;" : "=f"(lo), "=f"(hi) : "l"(a)); return lo + hi;
}
__device__ __forceinline__ float ex2f(float x) { float y; asm("ex2.approx.f32 %0, %1;" : "=f"(y) : "f"(x)); return y; }
__device__ __forceinline__ float rcpf(float x) { float y; asm("rcp.approx.f32 %0, %1;" : "=f"(y) : "f"(x)); return y; }

__device__ __forceinline__ float act(float x, float aa, float bb, float cc) {
    return fmaf(aa, rcpf(1.0f + ex2f(bb * x)), cc);
}
__device__ __forceinline__ float tanh_(float x) {
    return fmaf(-2.0f, rcpf(ex2f(2.8853900817779268f * x) + 1.0f), 1.0f);
}

// One element's fused gate phase. Inlined; weight arrays stay in registers.
__device__ __forceinline__ void gate_phase(
    const ull* __restrict__ w1p, const ull* __restrict__ w2ip,
    const ull* __restrict__ w2hp,
    const ulonglong2* __restrict__ h1p, const ulonglong2* __restrict__ h2p,
    float xw_bias1, float bias2, float aa, float bb, float cc,
    float* __restrict__ g1dst, float* __restrict__ g2dst,
    bool doL1, bool doL2)
{
    ull a0 = 0ull, a1 = 0ull;   // L1: w_hh1 . h1
    ull e0 = 0ull, e1 = 0ull;   // L2: w_ih2 . h1 (reuses same h1 loads)
    ull d0 = 0ull, d1 = 0ull;   // L2: w_hh2 . h2
    #pragma unroll
    for (int k = 0; k < 7; k++) {
        ulonglong2 v1 = h1p[k];
        ulonglong2 v2 = h2p[k];
        fma2(a0, w1p[2 * k],      v1.x);
        fma2(a1, w1p[2 * k + 1],  v1.y);
        fma2(e0, w2ip[2 * k],     v1.x);
        fma2(e1, w2ip[2 * k + 1], v1.y);
        fma2(d0, w2hp[2 * k],     v2.x);
        fma2(d1, w2hp[2 * k + 1], v2.y);
    }
    {
        ull v1t = ((const ull*)h1p)[14], v2t = ((const ull*)h2p)[14];
        fma2(a0, w1p[14],  v1t);
        fma2(e0, w2ip[14], v1t);
        fma2(d0, w2hp[14], v2t);
    }
    if (doL1) *g1dst = act(xw_bias1 + hadd(add2(a0, a1)), aa, bb, cc);
    if (doL2) *g2dst = act(bias2 + hadd(add2(add2(e0, e1), add2(d0, d1))), aa, bb, cc);
}

__global__ void __launch_bounds__(128, 2) lstm_kernel(
    const float* __restrict__ x,
    const float* __restrict__ w_ih1, const float* __restrict__ w_hh1,
    const float* __restrict__ b_ih1, const float* __restrict__ b_hh1,
    const float* __restrict__ w_ih2, const float* __restrict__ w_hh2,
    const float* __restrict__ b_ih2, const float* __restrict__ b_hh2,
    const float* __restrict__ w_fc,  const float* __restrict__ b_fc,
    float* __restrict__ out)
{
    __shared__ __align__(16) float sxA[Ts], sxB[Ts];
    __shared__ __align__(16) float sh1[2][4][32];     // [elem][warp][unit]
    __shared__ __align__(16) float sh2[2][4][32];
    __shared__ __align__(16) float sg[2][2][2][128];  // [buf][elem][layer][u*4+w]

    const int tid = threadIdx.x;
    const int w   = tid >> 5;
    const int u   = tid & 31;
    const int bA  = blockIdx.x * 2;
    const int bB  = bA + 1;

    {   // coalesced x preload for both elements
        const float4* xa = (const float4*)(x + (size_t)bA * Ts);
        const float4* xb = (const float4*)(x + (size_t)bB * Ts);
        float4* sa = (float4*)sxA;
        float4* sb = (float4*)sxB;
        #pragma unroll
        for (int i = 0; i < Ts / 4 / 128; i++) {
            sa[tid + i * 128] = xa[tid + i * 128];
            sb[tid + i * 128] = xb[tid + i * 128];
        }
    }
    sh1[0][w][u] = 0.0f; sh1[1][w][u] = 0.0f;
    sh2[0][w][u] = 0.0f; sh2[1][w][u] = 0.0f;

    // Shared (across both elements) register-resident weights.
    const int row = w * Hs + ((u < Hs) ? u : Hs - 1);
    ull w1p[15], w2ip[15], w2hp[15];
    {
        const float* r1  = w_hh1 + row * Hs;
        const float* r2i = w_ih2 + row * Hs;
        const float* r2h = w_hh2 + row * Hs;
        #pragma unroll
        for (int k = 0; k < 15; k++) {
            w1p[k]  = pk(r1[2 * k],  r1[2 * k + 1]);
            w2ip[k] = pk(r2i[2 * k], r2i[2 * k + 1]);
            w2hp[k] = pk(r2h[2 * k], r2h[2 * k + 1]);
        }
    }
    const float bias1 = b_ih1[row] + b_hh1[row];
    const float bias2 = b_ih2[row] + b_hh2[row];
    const float wx    = w_ih1[row];
    const float wfc   = (u < Hs) ? w_fc[u] : 0.0f;
    const float bfc   = b_fc[0];

    const float aa = (w == 2) ? 2.0f : 1.0f;
    const float bb = (w == 2) ? -2.8853900817779268f : -1.4426950408889634f;
    const float cc = (w == 2) ? -1.0f : 0.0f;

    float c1A = 0.0f, c2A = 0.0f, c1B = 0.0f, c2B = 0.0f;
    float* outA = out + (size_t)bA * Ts;
    float* outB = out + (size_t)bB * Ts;

    const ulonglong2* h1pA = (const ulonglong2*)sh1[0][w];
    const ulonglong2* h2pA = (const ulonglong2*)sh2[0][w];
    const ulonglong2* h1pB = (const ulonglong2*)sh1[1][w];
    const ulonglong2* h2pB = (const ulonglong2*)sh2[1][w];

    const int gidx = 4 * u + w;

    __syncthreads();

    // ---- Peeled t = 0: L1 gates/state only ----
    {
        float* gA = &sg[0][0][0][0];
        float* gB = &sg[0][1][0][0];
        gate_phase(w1p, w2ip, w2hp, h1pA, h2pA, fmaf(sxA[0], wx, bias1), bias2,
                   aa, bb, cc, gA + gidx, gA + 128 + gidx, true, false);
        gate_phase(w1p, w2ip, w2hp, h1pB, h2pB, fmaf(sxB[0], wx, bias1), bias2,
                   aa, bb, cc, gB + gidx, gB + 128 + gidx, true, false);
        __syncthreads();
        {
            float4 g = *(const float4*)(gA + 4 * u);
            c1A = fmaf(g.y, c1A, g.x * g.z);
            sh1[0][w][u] = g.w * tanh_(c1A);
        }
        {
            float4 g = *(const float4*)(gB + 4 * u);
            c1B = fmaf(g.y, c1B, g.x * g.z);
            sh1[1][w][u] = g.w * tanh_(c1B);
        }
        __syncwarp();
    }

    // ---- Steady state: t = 1 .. Ts-1, both layers active ----
    #pragma unroll 2
    for (int t = 1; t < Ts; t++) {
        float* gA = &sg[t & 1][0][0][0];
        float* gB = &sg[t & 1][1][0][0];

        gate_phase(w1p, w2ip, w2hp, h1pA, h2pA, fmaf(sxA[t], wx, bias1), bias2,
                   aa, bb, cc, gA + gidx, gA + 128 + gidx, true, true);
        gate_phase(w1p, w2ip, w2hp, h1pB, h2pB, fmaf(sxB[t], wx, bias1), bias2,
                   aa, bb, cc, gB + gidx, gB + 128 + gidx, true, true);
        __syncthreads();

        // state L1 (step t) + L2 (step t-1), both elements, redundant per warp
        {
            float4 g = *(const float4*)(gA + 4 * u);
            c1A = fmaf(g.y, c1A, g.x * g.z);
            sh1[0][w][u] = g.w * tanh_(c1A);
        }
        {
            float4 g = *(const float4*)(gB + 4 * u);
            c1B = fmaf(g.y, c1B, g.x * g.z);
            sh1[1][w][u] = g.w * tanh_(c1B);
        }
        {
            float4 g = *(const float4*)(gA + 128 + 4 * u);
            c2A = fmaf(g.y, c2A, g.x * g.z);
            float h2v = g.w * tanh_(c2A);
            sh2[0][w][u] = h2v;
            if (w == 0) {
                float p = wfc * h2v;
                #pragma unroll
                for (int s = 16; s; s >>= 1) p += __shfl_xor_sync(0xffffffffu, p, s);
                if (u == 0) outA[t - 1] = p + bfc;
            }
        }
        {
            float4 g = *(const float4*)(gB + 128 + 4 * u);
            c2B = fmaf(g.y, c2B, g.x * g.z);
            float h2v = g.w * tanh_(c2B);
            sh2[1][w][u] = h2v;
            if (w == 1) {
                float p = wfc * h2v;
                #pragma unroll
                for (int s = 16; s; s >>= 1) p += __shfl_xor_sync(0xffffffffu, p, s);
                if (u == 0) outB[t - 1] = p + bfc;
            }
        }
        __syncwarp();
    }

    // ---- Peeled t = Ts: L2 gates/state only ----
    {
        float* gA = &sg[Ts & 1][0][0][0];
        float* gB = &sg[Ts & 1][1][0][0];
        gate_phase(w1p, w2ip, w2hp, h1pA, h2pA, 0.0f, bias2,
                   aa, bb, cc, gA + gidx, gA + 128 + gidx, false, true);
        gate_phase(w1p, w2ip, w2hp, h1pB, h2pB, 0.0f, bias2,
                   aa, bb, cc, gB + gidx, gB + 128 + gidx, false, true);
        __syncthreads();
        {
            float4 g = *(const float4*)(gA + 128 + 4 * u);
            c2A = fmaf(g.y, c2A, g.x * g.z);
            float h2v = g.w * tanh_(c2A);
            if (w == 0) {
                float p = wfc * h2v;
                #pragma unroll
                for (int s = 16; s; s >>= 1) p += __shfl_xor_sync(0xffffffffu, p, s);
                if (u == 0) outA[Ts - 1] = p + bfc;
            }
        }
        {
            float4 g = *(const float4*)(gB + 128 + 4 * u);
            c2B = fmaf(g.y, c2B, g.x * g.z);
            float h2v = g.w * tanh_(c2B);
            if (w == 1) {
                float p = wfc * h2v;
                #pragma unroll
                for (int s = 16; s; s >>= 1) p += __shfl_xor_sync(0xffffffffu, p, s);
                if (u == 0) outB[Ts - 1] = p + bfc;
            }
        }
    }
}

extern "C" void kernel_launch(void* const* d_in, const int* in_sizes, int n_in,
                              void* d_out, int out_size) {
    (void)in_sizes; (void)n_in; (void)out_size;
    lstm_kernel<<<Bs / 2, 128>>>(
        (const float*)d_in[0],
        (const float*)d_in[1], (const float*)d_in[2],
        (const float*)d_in[3], (const float*)d_in[4],
        (const float*)d_in[5], (const float*)d_in[6],
        (const float*)d_in[7], (const float*)d_in[8],
        (const float*)d_in[9], (const float*)d_in[10],
        (float*)d_out);
}

// round 5
// speedup vs baseline: 1.2281x; 1.2281x over previous
#include <cuda_runtime.h>

// 2-layer LSTM (H=30, IN=1) + linear head, B=512, T=2048.
// R3 structure (best so far): block = 1 batch element, 128 thr = 4 warps;
// warp w owns gate TYPE w (0=i,1=f,2=g,3=o), lane u owns unit u; weight rows
// register-resident (f32x2). Layer-pipelined: iteration t does L1 gates for
// step t + L2 gates for step t-1 -> ONE __syncthreads per step, gates
// double-buffered. This round: steady loop hand-unrolled x2 with the two gate
// buffers as distinct compile-time pointers (kills all t&1 address ALU),
// pointer-advanced x loads, fully peeled prologue/epilogue (no predicates).

#define Hs 30
#define Ts 2048
#define Bs 512

typedef unsigned long long ull;

__device__ __forceinline__ ull pk(float lo, float hi) {
    ull r; asm("mov.b64 %0, {%1, %2};" : "=l"(r) : "f"(lo), "f"(hi)); return r;
}
__device__ __forceinline__ void fma2(ull& d, ull a, ull b) {
    asm("fma.rn.f32x2 %0, %1, %2, %3;" : "=l"(d) : "l"(a), "l"(b), "l"(d));
}
__device__ __forceinline__ ull add2(ull a, ull b) {
    ull r; asm("add.rn.f32x2 %0, %1, %2;" : "=l"(r) : "l"(a), "l"(b)); return r;
}
__device__ __forceinline__ float hadd(ull a) {
    float lo, hi; asm("mov.b64 {%0, %1}, %2;" : "=f"(lo), "=f"(hi) : "l"(a)); return lo + hi;
}
__device__ __forceinline__ float ex2f(float x) { float y; asm("ex2.approx.f32 %0, %1;" : "=f"(y) : "f"(x)); return y; }
__device__ __forceinline__ float rcpf(float x) { float y; asm("rcp.approx.f32 %0, %1;" : "=f"(y) : "f"(x)); return y; }

__device__ __forceinline__ float act(float x, float aa, float bb, float cc) {
    return fmaf(aa, rcpf(1.0f + ex2f(bb * x)), cc);
}
__device__ __forceinline__ float tanh_(float x) {
    return fmaf(-2.0f, rcpf(ex2f(2.8853900817779268f * x) + 1.0f), 1.0f);
}

// Full gate phase for one step: L1 pre-activation (needs x[t]) + L2 pre-act.
#define GATE_BOTH(XV, GB) { \
    ull a0 = 0ull, a1 = 0ull, e0 = 0ull, e1 = 0ull, d0 = 0ull, d1 = 0ull; \
    _Pragma("unroll") \
    for (int k = 0; k < 7; k++) { \
        ulonglong2 v1 = h1p[k]; \
        ulonglong2 v2 = h2p[k]; \
        fma2(a0, w1p[2 * k],      v1.x); \
        fma2(a1, w1p[2 * k + 1],  v1.y); \
        fma2(e0, w2ip[2 * k],     v1.x); \
        fma2(e1, w2ip[2 * k + 1], v1.y); \
        fma2(d0, w2hp[2 * k],     v2.x); \
        fma2(d1, w2hp[2 * k + 1], v2.y); \
    } \
    { ull v1t = ((const ull*)h1p)[14], v2t = ((const ull*)h2p)[14]; \
      fma2(a0, w1p[14],  v1t); \
      fma2(e0, w2ip[14], v1t); \
      fma2(d0, w2hp[14], v2t); } \
    (GB)[gidx]       = act(fmaf((XV), wx, bias1) + hadd(add2(a0, a1)), aa, bb, cc); \
    (GB)[128 + gidx] = act(bias2 + hadd(add2(add2(e0, e1), add2(d0, d1))), aa, bb, cc); \
}

// Full state phase: L1 state for step t, L2 state (+ FC output) for step t-1.
#define STATE_BOTH(GB, OUTP) { \
    float4 g = *(const float4*)((GB) + 4 * u); \
    c1 = fmaf(g.y, c1, g.x * g.z); \
    sh1u[0] = g.w * tanh_(c1); \
    float4 q = *(const float4*)((GB) + 128 + 4 * u); \
    c2 = fmaf(q.y, c2, q.x * q.z); \
    float h2v = q.w * tanh_(c2); \
    sh2u[0] = h2v; \
    if (w == 0) { \
        float p = wfc * h2v; \
        _Pragma("unroll") \
        for (int s = 16; s; s >>= 1) p += __shfl_xor_sync(0xffffffffu, p, s); \
        if (u == 0) (OUTP) = p + bfc; \
    } \
}

__global__ void __launch_bounds__(128, 4) lstm_kernel(
    const float* __restrict__ x,
    const float* __restrict__ w_ih1, const float* __restrict__ w_hh1,
    const float* __restrict__ b_ih1, const float* __restrict__ b_hh1,
    const float* __restrict__ w_ih2, const float* __restrict__ w_hh2,
    const float* __restrict__ b_ih2, const float* __restrict__ b_hh2,
    const float* __restrict__ w_fc,  const float* __restrict__ b_fc,
    float* __restrict__ out)
{
    __shared__ __align__(16) float sx[Ts];        // x row for this batch element
    __shared__ __align__(16) float sh1w[4][32];   // per-warp private h1 copy
    __shared__ __align__(16) float sh2w[4][32];   // per-warp private h2 copy
    __shared__ __align__(16) float sgA[256];      // gate buffer, even iters
    __shared__ __align__(16) float sgB[256];      // gate buffer, odd iters

    const int tid = threadIdx.x;
    const int w   = tid >> 5;
    const int u   = tid & 31;
    const int b   = blockIdx.x;

    {   // coalesced x preload
        const float4* xb4 = (const float4*)(x + (size_t)b * Ts);
        float4* sx4 = (float4*)sx;
        #pragma unroll
        for (int i = 0; i < Ts / 4 / 128; i++) sx4[tid + i * 128] = xb4[tid + i * 128];
    }
    sh1w[w][u] = 0.0f;
    sh2w[w][u] = 0.0f;

    const int row = w * Hs + ((u < Hs) ? u : Hs - 1);
    ull w1p[15], w2ip[15], w2hp[15];
    {
        const float* r1  = w_hh1 + row * Hs;
        const float* r2i = w_ih2 + row * Hs;
        const float* r2h = w_hh2 + row * Hs;
        #pragma unroll
        for (int k = 0; k < 15; k++) {
            w1p[k]  = pk(r1[2 * k],  r1[2 * k + 1]);
            w2ip[k] = pk(r2i[2 * k], r2i[2 * k + 1]);
            w2hp[k] = pk(r2h[2 * k], r2h[2 * k + 1]);
        }
    }
    const float bias1 = b_ih1[row] + b_hh1[row];
    const float bias2 = b_ih2[row] + b_hh2[row];
    const float wx    = w_ih1[row];
    const float wfc   = (u < Hs) ? w_fc[u] : 0.0f;
    const float bfc   = b_fc[0];

    const float aa = (w == 2) ? 2.0f : 1.0f;
    const float bb = (w == 2) ? -2.8853900817779268f : -1.4426950408889634f;
    const float cc = (w == 2) ? -1.0f : 0.0f;

    float c1 = 0.0f, c2 = 0.0f;
    float* __restrict__ outb = out + (size_t)b * Ts;

    const ulonglong2* h1p = (const ulonglong2*)sh1w[w];
    const ulonglong2* h2p = (const ulonglong2*)sh2w[w];
    float* const sh1u = &sh1w[w][u];
    float* const sh2u = &sh2w[w][u];
    const int gidx = 4 * u + w;

    __syncthreads();

    // ---- Peeled t = 0: L1 only (h2 dot skipped) ----
    {
        ull a0 = 0ull, a1 = 0ull;
        #pragma unroll
        for (int k = 0; k < 7; k++) {
            ulonglong2 v1 = h1p[k];
            fma2(a0, w1p[2 * k],     v1.x);
            fma2(a1, w1p[2 * k + 1], v1.y);
        }
        fma2(a0, w1p[14], ((const ull*)h1p)[14]);
        sgA[gidx] = act(fmaf(sx[0], wx, bias1) + hadd(add2(a0, a1)), aa, bb, cc);
        __syncthreads();
        float4 g = *(const float4*)(sgA + 4 * u);
        c1 = fmaf(g.y, c1, g.x * g.z);
        sh1u[0] = g.w * tanh_(c1);
        __syncwarp();
    }

    // ---- Steady state: t = 1 .. 2046 in pairs (odd buf, even buf) ----
    const float* sxp = sx + 1;
    float* op = outb;          // op[0] <- out[t-1] for the odd step
    #pragma unroll 1
    for (int it = 0; it < (Ts - 2) / 2; it++) {
        // step t (odd) -> buffer B
        GATE_BOTH(sxp[0], sgB);
        __syncthreads();
        STATE_BOTH(sgB, op[0]);
        __syncwarp();
        // step t+1 (even) -> buffer A
        GATE_BOTH(sxp[1], sgA);
        __syncthreads();
        STATE_BOTH(sgA, op[1]);
        __syncwarp();
        sxp += 2;
        op  += 2;
    }

    // ---- t = 2047 (odd) -> buffer B ----
    GATE_BOTH(sxp[0], sgB);
    __syncthreads();
    STATE_BOTH(sgB, op[0]);
    __syncwarp();

    // ---- Peeled t = Ts: L2 only (consumes h1[2047], h2[2046]) ----
    {
        ull e0 = 0ull, e1 = 0ull, d0 = 0ull, d1 = 0ull;
        #pragma unroll
        for (int k = 0; k < 7; k++) {
            ulonglong2 v1 = h1p[k];
            ulonglong2 v2 = h2p[k];
            fma2(e0, w2ip[2 * k],     v1.x);
            fma2(e1, w2ip[2 * k + 1], v1.y);
            fma2(d0, w2hp[2 * k],     v2.x);
            fma2(d1, w2hp[2 * k + 1], v2.y);
        }
        {
            ull v1t = ((const ull*)h1p)[14], v2t = ((const ull*)h2p)[14];
            fma2(e0, w2ip[14], v1t);
            fma2(d0, w2hp[14], v2t);
        }
        sgA[128 + gidx] = act(bias2 + hadd(add2(add2(e0, e1), add2(d0, d1))), aa, bb, cc);
        __syncthreads();
        float4 q = *(const float4*)(sgA + 128 + 4 * u);
        c2 = fmaf(q.y, c2, q.x * q.z);
        float h2v = q.w * tanh_(c2);
        if (w == 0) {
            float p = wfc * h2v;
            #pragma unroll
            for (int s = 16; s; s >>= 1) p += __shfl_xor_sync(0xffffffffu, p, s);
            if (u == 0) outb[Ts - 1] = p + bfc;
        }
    }
}

extern "C" void kernel_launch(void* const* d_in, const int* in_sizes, int n_in,
                              void* d_out, int out_size) {
    (void)in_sizes; (void)n_in; (void)out_size;
    lstm_kernel<<<Bs, 128>>>(
        (const float*)d_in[0],
        (const float*)d_in[1], (const float*)d_in[2],
        (const float*)d_in[3], (const float*)d_in[4],
        (const float*)d_in[5], (const float*)d_in[6],
        (const float*)d_in[7], (const float*)d_in[8],
        (const float*)d_in[9], (const float*)d_in[10],
        (float*)d_out);
}